// round 4
// baseline (speedup 1.0000x reference)
#include <cuda_runtime.h>
#include <cuda_bf16.h>
#include <cstdint>

// Problem constants
#define BB 512      // batch
#define TT 365      // time steps
#define CC 10       // channels
#define PP 64       // prototypes
#define KK 3650     // T*C
#define KREAL 4015  // 3650 + 365
#define KPAD 4096
#define NKS 32      // K-split chunks (128 deep each)

// Output layout (float32, concatenated in reference return order)
#define O_OUTSEQ 0
#define O_INSEQ  1868800
#define O_DIST   3737600
#define O_IDX    3770368
#define O_LABEL  3770880
#define O_MASK   3771392

// ---------------- scratch (device globals; no allocation allowed) ----------
__device__ float g_Wt[KPAD * PP];           // W^T, k-major: [k][p]  (1 MB)
__device__ float g_part[NKS * BB * PP];     // K-split partials [ks][b][p] (4 MB)
__device__ float g_x2p[BB * NKS];           // x2 partials [b][ks]

// ---------------- packed f32x2 helpers -------------------------------------
__device__ __forceinline__ void fma2(unsigned long long& d,
                                     unsigned long long a,
                                     unsigned long long b) {
    asm("fma.rn.f32x2 %0, %1, %2, %0;" : "+l"(d) : "l"(a), "l"(b));
}
__device__ __forceinline__ unsigned long long pack2(float x) {
    unsigned long long r;
    asm("mov.b64 %0, {%1, %1};" : "=l"(r) : "f"(x));
    return r;
}

// ---------------- build W^T (k-major) via 32x32 smem transpose -------------
__global__ void k_buildW(const float* __restrict__ proto) {
    __shared__ float tile[32][33];
    int k0 = blockIdx.x * 32;
    int p0 = blockIdx.y * 32;
    int tx = threadIdx.x & 31;
    int ty = threadIdx.x >> 5;      // 0..7

    #pragma unroll
    for (int i = 0; i < 4; i++) {
        int p = p0 + ty + i * 8;
        int k = k0 + tx;
        float v = 0.0f;
        if (k < KK) {
            v = -2.0f * proto[p * KK + k];
        } else if (k < KREAL) {
            int t = k - KK;
            float s = 0.0f;
            #pragma unroll
            for (int c = 0; c < CC; c++) {
                float q = proto[p * KK + t * CC + c];
                s += q * q;
            }
            v = s;
        }
        tile[ty + i * 8][tx] = v;
    }
    __syncthreads();
    #pragma unroll
    for (int i = 0; i < 4; i++) {
        int k = k0 + ty + i * 8;
        g_Wt[k * PP + p0 + tx] = tile[tx][ty + i * 8];
    }
}

// ---------------- fused GEMM: stages virtual A on the fly ------------------
// chunk = 128 (4 halves of 32), BM=128, BN=64, 256 threads, 4x8 f32x2 tile.
__global__ void __launch_bounds__(256, 3) k_gemm(const float* __restrict__ x,
                                                 const float* __restrict__ mask) {
    __shared__ float As[128][33];   // 16.9 KB (one 32-deep half)
    __shared__ float Ws[32][64];    //  8 KB   (one 32-deep half)
    int ks = blockIdx.x;            // 0..31
    int k0 = ks * 128;
    int b0 = blockIdx.y * 128;
    int tid = threadIdx.x;
    int tb = tid & 31;              // b = b0 + tb + 32j
    int tp = tid >> 5;              // p = tp*8 + i

    unsigned long long acc2[4][4];
    #pragma unroll
    for (int j = 0; j < 4; j++)
        #pragma unroll
        for (int i = 0; i < 4; i++) acc2[j][i] = 0ull;
    float x2a[4] = {0.f, 0.f, 0.f, 0.f};

    int kloc = tid & 31;            // staging: k within half
    int brow0 = tid >> 5;           // staging: b row base (0..7)

    for (int h = 0; h < 4; h++) {
        int kh = k0 + h * 32;
        if (h) __syncthreads();

        // stage W half: 32x64 = 512 float4 / 256 threads = 2 each
        #pragma unroll
        for (int i = 0; i < 2; i++) {
            int e = tid + i * 256;
            int row = e >> 4;
            int c4 = e & 15;
            float4 v = *reinterpret_cast<const float4*>(&g_Wt[(kh + row) * PP + c4 * 4]);
            *reinterpret_cast<float4*>(&Ws[row][c4 * 4]) = v;
        }
        // stage A half: 128 rows x 32 cols
        int k = kh + kloc;
        bool isx = (k < KK);
        bool ism = (!isx) && (k < KREAL);
        int t = isx ? (k / CC) : (k - KK);
        #pragma unroll
        for (int i = 0; i < 16; i++) {
            int brow = brow0 + i * 8;
            int b = b0 + brow;
            float v = 0.0f;
            if (isx)      v = x[b * KK + k] * __ldg(&mask[b * TT + t]);
            else if (ism) v = __ldg(&mask[b * TT + t]);
            As[brow][kloc] = v;
        }
        __syncthreads();

        #pragma unroll 8
        for (int kk = 0; kk < 32; kk++) {
            float a[4];
            #pragma unroll
            for (int j = 0; j < 4; j++) a[j] = As[tb + 32 * j][kk];
            const unsigned long long* wp =
                reinterpret_cast<const unsigned long long*>(&Ws[kk][tp * 8]);
            unsigned long long w0 = wp[0], w1 = wp[1], w2 = wp[2], w3 = wp[3];
            #pragma unroll
            for (int j = 0; j < 4; j++) {
                unsigned long long aj = pack2(a[j]);
                fma2(acc2[j][0], aj, w0);
                fma2(acc2[j][1], aj, w1);
                fma2(acc2[j][2], aj, w2);
                fma2(acc2[j][3], aj, w3);
            }
            if (tp == 0 && (kh + kk) < KK) {
                #pragma unroll
                for (int j = 0; j < 4; j++) x2a[j] += a[j] * a[j];
            }
        }
    }

    #pragma unroll
    for (int j = 0; j < 4; j++) {
        int b = b0 + tb + 32 * j;
        float2 p0v = *reinterpret_cast<float2*>(&acc2[j][0]);
        float2 p1v = *reinterpret_cast<float2*>(&acc2[j][1]);
        float2 p2v = *reinterpret_cast<float2*>(&acc2[j][2]);
        float2 p3v = *reinterpret_cast<float2*>(&acc2[j][3]);
        float* dst = &g_part[(ks * BB + b) * PP + tp * 8];
        *reinterpret_cast<float4*>(dst)     = make_float4(p0v.x, p0v.y, p1v.x, p1v.y);
        *reinterpret_cast<float4*>(dst + 4) = make_float4(p2v.x, p2v.y, p3v.x, p3v.y);
    }
    if (tp == 0) {
        #pragma unroll
        for (int j = 0; j < 4; j++)
            g_x2p[(b0 + tb + 32 * j) * NKS + ks] = x2a[j];
    }
}

// ---------------- fused epilogue -------------------------------------------
// blocks 0..511:    per-b reduce + argmin + dist/idx/label + gather proto row
// blocks 512..1023: flat float4 copy of input_seq and mask regions
#define FLAT_X4   467200               // BB*KK/4
#define FLAT_M4   46720                // BB*TT/4
#define FLAT_TOT  (FLAT_X4 + FLAT_M4)

__global__ void __launch_bounds__(256) k_epilogue(const float* __restrict__ x,
                                                  const float* __restrict__ mask,
                                                  const int* __restrict__ label,
                                                  const float* __restrict__ proto,
                                                  float* __restrict__ out) {
    int tid = threadIdx.x;
    if (blockIdx.x >= BB) {
        // ---- flat copies: x -> O_INSEQ, mask -> O_MASK (both 16B aligned) --
        int nblk = gridDim.x - BB;
        const float4* xs = reinterpret_cast<const float4*>(x);
        const float4* ms = reinterpret_cast<const float4*>(mask);
        float4* dx = reinterpret_cast<float4*>(out + O_INSEQ);
        float4* dm = reinterpret_cast<float4*>(out + O_MASK);
        int stride = nblk * 256;
        for (int i = (blockIdx.x - BB) * 256 + tid; i < FLAT_TOT; i += stride) {
            if (i < FLAT_X4) dx[i] = xs[i];
            else             dm[i - FLAT_X4] = ms[i - FLAT_X4];
        }
        return;
    }

    __shared__ float sp[4][64];
    __shared__ float sx0;
    __shared__ float sv[64];
    __shared__ int si[64];
    __shared__ int sidx;
    int b = blockIdx.x;
    int pp = tid & 63;
    int g = tid >> 6;                  // 0..3: each sums 8 ks chunks

    float acc = 0.0f;
    #pragma unroll
    for (int i = 0; i < 8; i++) {
        int ks = g * 8 + i;
        acc += g_part[(ks * BB + b) * PP + pp];
    }
    sp[g][pp] = acc;
    __syncthreads();

    if (tid < 32) {                    // x2 = sum of 32 chunk partials
        float v = g_x2p[b * NKS + tid];
        #pragma unroll
        for (int s = 16; s > 0; s >>= 1)
            v += __shfl_xor_sync(0xffffffff, v, s);
        if (tid == 0) sx0 = v;
    }
    __syncthreads();

    if (tid < 64) {
        float tot = sp[0][pp] + sp[1][pp] + sp[2][pp] + sp[3][pp] + sx0;
        out[O_DIST + b * PP + pp] = tot;
        sv[pp] = tot;
        si[pp] = pp;
    }
    __syncthreads();
    for (int s = 32; s > 0; s >>= 1) {
        if (tid < s) {
            float ov = sv[tid + s];
            int oi = si[tid + s];
            if (ov < sv[tid] || (ov == sv[tid] && oi < si[tid])) {
                sv[tid] = ov;
                si[tid] = oi;
            }
        }
        __syncthreads();
    }
    if (tid == 0) {
        sidx = si[0];
        out[O_IDX + b] = (float)si[0];
        out[O_LABEL + b] = (float)label[b];
    }
    __syncthreads();

    // ---- gather selected prototype row (rows are 8B-aligned) -------------
    int idx = sidx;
    const float2* src = reinterpret_cast<const float2*>(proto + idx * KK);
    float2* d0 = reinterpret_cast<float2*>(out + O_OUTSEQ + b * KK);
    #pragma unroll 4
    for (int i = tid; i < KK / 2; i += 256)
        d0[i] = src[i];
}

// ---------------- launcher --------------------------------------------------
extern "C" void kernel_launch(void* const* d_in, const int* in_sizes, int n_in,
                              void* d_out, int out_size) {
    const float* x     = (const float*)d_in[0];  // [B,T,C]
    const float* mask  = (const float*)d_in[1];  // [B,T]
    const int*   label = (const int*)d_in[2];    // [B]
    const float* proto = (const float*)d_in[3];  // [P,T,C]
    float* out = (float*)d_out;

    k_buildW<<<dim3(KPAD / 32, PP / 32), 256>>>(proto);
    k_gemm<<<dim3(NKS, 4), 256>>>(x, mask);
    k_epilogue<<<1024, 256>>>(x, mask, label, proto, out);
}